// round 6
// baseline (speedup 1.0000x reference)
#include <cuda_runtime.h>
#include <cuda_bf16.h>
#include <math.h>
#include <stdint.h>

#define NH     16
#define NKV    4
#define HDIM   128
#define BATCH  2
#define SEQ    2048
#define DMODEL 2048
#define NTOK   (BATCH*SEQ)

// ---------------------------------------------------------------------------
// scratch
// ---------------------------------------------------------------------------
static __device__ float g_q[NTOK * NH * HDIM];
static __device__ float g_k[NTOK * NKV * HDIM];

static __device__ __nv_bfloat16 g_qh[NTOK * NH * HDIM];
static __device__ __nv_bfloat16 g_ql[NTOK * NH * HDIM];
static __device__ __nv_bfloat16 g_kbh[NTOK * NKV * HDIM];
static __device__ __nv_bfloat16 g_kbl[NTOK * NKV * HDIM];
static __device__ __nv_bfloat16 g_vbh[NTOK * NKV * HDIM];
static __device__ __nv_bfloat16 g_vbl[NTOK * NKV * HDIM];

static __device__ __nv_bfloat16 g_xh[NTOK * DMODEL];
static __device__ __nv_bfloat16 g_xl[NTOK * DMODEL];
static __device__ __nv_bfloat16 g_cth[NTOK * DMODEL];
static __device__ __nv_bfloat16 g_ctl[NTOK * DMODEL];
static __device__ __nv_bfloat16 g_wqh[DMODEL * (NH*HDIM)];
static __device__ __nv_bfloat16 g_wql[DMODEL * (NH*HDIM)];
static __device__ __nv_bfloat16 g_wkh[DMODEL * (NKV*HDIM)];
static __device__ __nv_bfloat16 g_wkl[DMODEL * (NKV*HDIM)];
static __device__ __nv_bfloat16 g_wvh[DMODEL * (NKV*HDIM)];
static __device__ __nv_bfloat16 g_wvl[DMODEL * (NKV*HDIM)];
static __device__ __nv_bfloat16 g_woh[DMODEL * DMODEL];
static __device__ __nv_bfloat16 g_wol[DMODEL * DMODEL];

// ---------------------------------------------------------------------------
// helpers
// ---------------------------------------------------------------------------
__device__ __forceinline__ uint32_t smem_u32(const void* p) {
  uint32_t a;
  asm("{ .reg .u64 t; cvta.to.shared.u64 t, %1; cvt.u32.u64 %0, t; }" : "=r"(a) : "l"(p));
  return a;
}

#define LDSM4(R, addr)                                                        \
  asm volatile("ldmatrix.sync.aligned.m8n8.x4.shared.b16 {%0,%1,%2,%3}, [%4];"\
    : "=r"((R)[0]), "=r"((R)[1]), "=r"((R)[2]), "=r"((R)[3]) : "r"(addr))

#define LDSM4T(R, addr)                                                       \
  asm volatile("ldmatrix.sync.aligned.m8n8.x4.trans.shared.b16 {%0,%1,%2,%3}, [%4];"\
    : "=r"((R)[0]), "=r"((R)[1]), "=r"((R)[2]), "=r"((R)[3]) : "r"(addr))

#define MMA16816(D, A, b0v, b1v)                                              \
  asm volatile("mma.sync.aligned.m16n8k16.row.col.f32.bf16.bf16.f32 "         \
    "{%0,%1,%2,%3}, {%4,%5,%6,%7}, {%8,%9}, {%0,%1,%2,%3};"                   \
    : "+f"((D)[0]), "+f"((D)[1]), "+f"((D)[2]), "+f"((D)[3])                  \
    : "r"((A)[0]), "r"((A)[1]), "r"((A)[2]), "r"((A)[3]), "r"(b0v), "r"(b1v))

#define CP_ASYNC16(dst, src) \
  asm volatile("cp.async.cg.shared.global [%0], [%1], 16;" :: "r"(dst), "l"(src))
#define CP_COMMIT() asm volatile("cp.async.commit_group;")

// ---------------------------------------------------------------------------
// split fp32 -> bf16 hi/lo
// ---------------------------------------------------------------------------
__global__ void __launch_bounds__(256) split_kernel(const float* __restrict__ src,
    __nv_bfloat16* __restrict__ hi, __nv_bfloat16* __restrict__ lo, int n) {
  int i = blockIdx.x * 256 + threadIdx.x;
  if (i < n) {
    float v = src[i];
    __nv_bfloat16 h = __float2bfloat16(v);
    hi[i] = h;
    lo[i] = __float2bfloat16(v - __bfloat162float(h));
  }
}

// W [K,N] fp32 -> transposed bf16 hi/lo [N,K]
__global__ void __launch_bounds__(256) wsplit_kernel(const float* __restrict__ W,
    __nv_bfloat16* __restrict__ th, __nv_bfloat16* __restrict__ tl, int K, int N) {
  __shared__ float t[32][33];
  int n0 = blockIdx.x * 32, k0 = blockIdx.y * 32;
  int x = threadIdx.x, y = threadIdx.y;  // 32 x 8
  #pragma unroll
  for (int i = 0; i < 4; i++)
    t[y * 4 + i][x] = W[(size_t)(k0 + y * 4 + i) * N + n0 + x];
  __syncthreads();
  #pragma unroll
  for (int i = 0; i < 4; i++) {
    int n = n0 + y * 4 + i;
    float v = t[x][y * 4 + i];
    __nv_bfloat16 h = __float2bfloat16(v);
    th[(size_t)n * K + k0 + x] = h;
    tl[(size_t)n * K + k0 + x] = __float2bfloat16(v - __bfloat162float(h));
  }
}

// ---------------------------------------------------------------------------
// Multistage mma.sync GEMM, bf16x3: C = A @ B^T.
// Term-major MMA emission: 16 independent MMAs between accumulator reuses.
// ---------------------------------------------------------------------------
#define GBM 128
#define GBN 128
#define GBK 32
#define RSTRIDE 80
#define TILE_BYTES (128 * RSTRIDE)
#define STG_BYTES (4 * TILE_BYTES)
#define GEMM_SMEM (4 * STG_BYTES)

__global__ void __launch_bounds__(256) gemm3_kernel(
    const __nv_bfloat16* __restrict__ Ah, const __nv_bfloat16* __restrict__ Al,
    const __nv_bfloat16* __restrict__ Bh, const __nv_bfloat16* __restrict__ Bl,
    float* __restrict__ Cf, __nv_bfloat16* __restrict__ Ch,
    __nv_bfloat16* __restrict__ Cl, int K, int N) {
  extern __shared__ char smem[];
  uint32_t sbase = smem_u32(smem);
  int tid = threadIdx.x;
  int wid = tid >> 5, lane = tid & 31;
  int wm = wid >> 1, wn = wid & 1;
  int bm = blockIdx.y * GBM, bn = blockIdx.x * GBN;
  int nc = K / GBK;

  const __nv_bfloat16* srcs[4] = {Ah, Al, Bh, Bl};
  int rbase[4] = {bm, bm, bn, bn};

  auto load_chunk = [&](int c, int buf) {
    int k0 = c * GBK;
    #pragma unroll
    for (int i = 0; i < 8; i++) {
      int idx = tid + i * 256;
      int t = i >> 1;
      int r = (idx >> 2) & 127;
      int g = idx & 3;
      uint32_t dst = sbase + buf * STG_BYTES + t * TILE_BYTES + r * RSTRIDE + g * 16;
      const __nv_bfloat16* src = srcs[t] + (size_t)(rbase[t] + r) * K + k0 + g * 8;
      CP_ASYNC16(dst, src);
    }
    CP_COMMIT();
  };

  float acc[2][8][4];
  #pragma unroll
  for (int mi = 0; mi < 2; mi++)
    #pragma unroll
    for (int ni = 0; ni < 8; ni++)
      #pragma unroll
      for (int j = 0; j < 4; j++) acc[mi][ni][j] = 0.f;

  load_chunk(0, 0);
  load_chunk(1, 1);
  load_chunk(2, 2);

  int lrow = lane & 15, lk8 = (lane >> 4) * 8;

  for (int c = 0; c < nc; c++) {
    asm volatile("cp.async.wait_group 2;");
    __syncthreads();
    if (c + 3 < nc) load_chunk(c + 3, (c + 3) & 3);
    else CP_COMMIT();

    uint32_t b0 = sbase + (c & 3) * STG_BYTES;
    uint32_t aHs = b0, aLs = b0 + TILE_BYTES;
    uint32_t bHs = b0 + 2 * TILE_BYTES, bLs = b0 + 3 * TILE_BYTES;

    #pragma unroll
    for (int kk = 0; kk < GBK; kk += 16) {
      uint32_t ah[2][4], al[2][4], h[4][4], l[4][4];
      uint32_t aoff = (uint32_t)(wm * 32 + lrow) * RSTRIDE + (kk + lk8) * 2;
      LDSM4(ah[0], aHs + aoff);
      LDSM4(ah[1], aHs + aoff + 16 * RSTRIDE);
      LDSM4(al[0], aLs + aoff);
      LDSM4(al[1], aLs + aoff + 16 * RSTRIDE);
      #pragma unroll
      for (int p = 0; p < 4; p++) {
        uint32_t boff = (uint32_t)(wn * 64 + p * 16 + lrow) * RSTRIDE + (kk + lk8) * 2;
        LDSM4(h[p], bHs + boff);
        LDSM4(l[p], bLs + boff);
      }
      // term-major: 16 independent MMAs between accumulator reuses
      #pragma unroll
      for (int p = 0; p < 4; p++)
        #pragma unroll
        for (int mi = 0; mi < 2; mi++) {
          MMA16816(acc[mi][2 * p],     ah[mi], h[p][0], h[p][2]);
          MMA16816(acc[mi][2 * p + 1], ah[mi], h[p][1], h[p][3]);
        }
      #pragma unroll
      for (int p = 0; p < 4; p++)
        #pragma unroll
        for (int mi = 0; mi < 2; mi++) {
          MMA16816(acc[mi][2 * p],     ah[mi], l[p][0], l[p][2]);
          MMA16816(acc[mi][2 * p + 1], ah[mi], l[p][1], l[p][3]);
        }
      #pragma unroll
      for (int p = 0; p < 4; p++)
        #pragma unroll
        for (int mi = 0; mi < 2; mi++) {
          MMA16816(acc[mi][2 * p],     al[mi], h[p][0], h[p][2]);
          MMA16816(acc[mi][2 * p + 1], al[mi], h[p][1], h[p][3]);
        }
    }
  }

  int gid = lane >> 2, cid = lane & 3;
  if (Cf) {
    #pragma unroll
    for (int mi = 0; mi < 2; mi++)
      #pragma unroll
      for (int ni = 0; ni < 8; ni++) {
        int row = bm + wm * 32 + mi * 16 + gid;
        int col = bn + wn * 64 + ni * 8 + cid * 2;
        *(float2*)(Cf + (size_t)row * N + col) =
            make_float2(acc[mi][ni][0], acc[mi][ni][1]);
        *(float2*)(Cf + (size_t)(row + 8) * N + col) =
            make_float2(acc[mi][ni][2], acc[mi][ni][3]);
      }
  } else {
    #pragma unroll
    for (int mi = 0; mi < 2; mi++)
      #pragma unroll
      for (int ni = 0; ni < 8; ni++) {
        int row = bm + wm * 32 + mi * 16 + gid;
        int col = bn + wn * 64 + ni * 8 + cid * 2;
        #pragma unroll
        for (int half = 0; half < 2; half++) {
          float v0 = acc[mi][ni][2 * half], v1 = acc[mi][ni][2 * half + 1];
          __nv_bfloat16 h0 = __float2bfloat16(v0), h1 = __float2bfloat16(v1);
          __nv_bfloat162 hh; hh.x = h0; hh.y = h1;
          __nv_bfloat162 ll;
          ll.x = __float2bfloat16(v0 - __bfloat162float(h0));
          ll.y = __float2bfloat16(v1 - __bfloat162float(h1));
          size_t o = (size_t)(row + half * 8) * N + col;
          *(__nv_bfloat162*)(Ch + o) = hh;
          *(__nv_bfloat162*)(Cl + o) = ll;
        }
      }
  }
}

// ---------------------------------------------------------------------------
// RoPE + L2 norm -> split bf16 q/k
// ---------------------------------------------------------------------------
__global__ void __launch_bounds__(64) rope_norm_kernel() {
  int tok = blockIdx.x;
  int r = blockIdx.y;
  size_t off = (r < NH) ? ((size_t)tok * NH + r) * HDIM
                        : ((size_t)tok * NKV + (r - NH)) * HDIM;
  const float* base = (r < NH) ? g_q + off : g_k + off;
  __nv_bfloat16* bh = (r < NH) ? g_qh + off : g_kbh + off;
  __nv_bfloat16* bl = (r < NH) ? g_ql + off : g_kbl + off;
  int pos = tok & (SEQ - 1);
  int i = threadIdx.x;
  float t0 = base[2 * i], t1 = base[2 * i + 1];
  float inv = exp2f((float)(2 * i) * (-13.287712379549449f / 128.0f));
  float ang = (float)pos * inv;
  float sn, cs;
  sincosf(ang, &sn, &cs);
  float r0 = t0 * cs - t1 * sn;
  float r1 = t0 * sn + t1 * cs;
  float ss = r0 * r0 + r1 * r1;
  #pragma unroll
  for (int o = 16; o; o >>= 1) ss += __shfl_xor_sync(0xffffffffu, ss, o);
  __shared__ float part[2];
  if ((i & 31) == 0) part[i >> 5] = ss;
  __syncthreads();
  float sc = rsqrtf((part[0] + part[1]) * (1.0f / 128.0f) + 1e-6f);
  float v0 = r0 * sc, v1 = r1 * sc;
  __nv_bfloat16 h0 = __float2bfloat16(v0), h1 = __float2bfloat16(v1);
  bh[2 * i] = h0; bh[2 * i + 1] = h1;
  bl[2 * i] = __float2bfloat16(v0 - __bfloat162float(h0));
  bl[2 * i + 1] = __float2bfloat16(v1 - __bfloat162float(h1));
}

// ---------------------------------------------------------------------------
// MMA attention, per-term accumulators (spacing 6)
// ---------------------------------------------------------------------------
#define SCW 2056
#define PAD_STR 272
#define OFF_QH 131584
#define OFF_QL (OFF_QH + 16*PAD_STR)
#define OFF_KH (OFF_QL + 16*PAD_STR)
#define OFF_KL (OFF_KH + 128*PAD_STR)
#define OFF_PH (OFF_KL + 128*PAD_STR)
#define OFF_PL (OFF_PH + 16*PAD_STR)
#define OFF_RED (OFF_PL + 16*PAD_STR)
#define ATTN_SMEM (OFF_RED + 128)

__global__ void __launch_bounds__(256, 1) attn_mma_kernel(
    float* __restrict__ attn_out, int write_attn) {
  extern __shared__ char smc[];
  float* s_scores = (float*)smc;
  float* s_red = (float*)(smc + OFF_RED);
  uint32_t sb = smem_u32(smc);

  int qb = gridDim.x - 1 - blockIdx.x;
  int h = blockIdx.y, b = blockIdx.z;
  int hk = h >> 2;
  int tid = threadIdx.x, w = tid >> 5, lane = tid & 31;
  int kend = qb * 16 + 16;
  const float SC = 0.08838834764831845f;
  int lrow = lane & 15, lhi = lane >> 4;

  {
    int r = tid >> 4, g = tid & 15;
    size_t go = ((size_t)(b * SEQ + qb * 16 + r) * NH + h) * HDIM + g * 8;
    *(uint4*)(smc + OFF_QH + r * PAD_STR + g * 16) = *(const uint4*)(g_qh + go);
    *(uint4*)(smc + OFF_QL + r * PAD_STR + g * 16) = *(const uint4*)(g_ql + go);
  }
  __syncthreads();

  uint32_t aH[8][4], aL[8][4];
  #pragma unroll
  for (int kk = 0; kk < 8; kk++) {
    uint32_t off = lrow * PAD_STR + kk * 32 + lhi * 16;
    LDSM4(aH[kk], sb + OFF_QH + off);
    LDSM4(aL[kk], sb + OFF_QL + off);
  }

  // ---- scores ----
  for (int kc = 0; kc < kend; kc += 128) {
    __syncthreads();
    for (int idx = tid; idx < 128 * 16; idx += 256) {
      int j = idx >> 4, g = idx & 15;
      uint4 vh = {0, 0, 0, 0}, vl = {0, 0, 0, 0};
      if (kc + j < kend) {
        size_t go = ((size_t)(b * SEQ + kc + j) * NKV + hk) * HDIM + g * 8;
        vh = *(const uint4*)(g_kbh + go);
        vl = *(const uint4*)(g_kbl + go);
      }
      *(uint4*)(smc + OFF_KH + j * PAD_STR + g * 16) = vh;
      *(uint4*)(smc + OFF_KL + j * PAD_STR + g * 16) = vl;
    }
    __syncthreads();

    float acc[3][2][4];
    #pragma unroll
    for (int t = 0; t < 3; t++)
      #pragma unroll
      for (int nt = 0; nt < 2; nt++)
        #pragma unroll
        for (int j = 0; j < 4; j++) acc[t][nt][j] = 0.f;
    int n0 = w * 16;
    #pragma unroll
    for (int kk = 0; kk < 8; kk++) {
      uint32_t off = (n0 + lrow) * PAD_STR + kk * 32 + lhi * 16;
      uint32_t bh[4], bl[4];
      LDSM4(bh, sb + OFF_KH + off);
      LDSM4(bl, sb + OFF_KL + off);
      MMA16816(acc[0][0], aH[kk], bh[0], bh[2]);
      MMA16816(acc[0][1], aH[kk], bh[1], bh[3]);
      MMA16816(acc[1][0], aH[kk], bl[0], bl[2]);
      MMA16816(acc[1][1], aH[kk], bl[1], bl[3]);
      MMA16816(acc[2][0], aL[kk], bh[0], bh[2]);
      MMA16816(acc[2][1], aL[kk], bh[1], bh[3]);
    }
    int r0 = lane >> 2, c0 = (lane & 3) * 2;
    int qs0 = qb * 16;
    #pragma unroll
    for (int nt = 0; nt < 2; nt++) {
      int col = kc + n0 + nt * 8 + c0;
      float e0 = acc[0][nt][0] + acc[1][nt][0] + acc[2][nt][0];
      float e1 = acc[0][nt][1] + acc[1][nt][1] + acc[2][nt][1];
      float e2 = acc[0][nt][2] + acc[1][nt][2] + acc[2][nt][2];
      float e3 = acc[0][nt][3] + acc[1][nt][3] + acc[2][nt][3];
      s_scores[r0 * SCW + col]           = (col     <= qs0 + r0)     ? e0 * SC : -1e30f;
      s_scores[r0 * SCW + col + 1]       = (col + 1 <= qs0 + r0)     ? e1 * SC : -1e30f;
      s_scores[(r0 + 8) * SCW + col]     = (col     <= qs0 + r0 + 8) ? e2 * SC : -1e30f;
      s_scores[(r0 + 8) * SCW + col + 1] = (col + 1 <= qs0 + r0 + 8) ? e3 * SC : -1e30f;
    }
  }
  __syncthreads();

  // ---- softmax stats ----
  {
    int qi = tid >> 4, r = tid & 15;
    float m = -1e30f;
    for (int j = r; j < kend; j += 16) m = fmaxf(m, s_scores[qi * SCW + j]);
    #pragma unroll
    for (int o = 8; o; o >>= 1) m = fmaxf(m, __shfl_xor_sync(0xffffffffu, m, o));
    float s = 0.f;
    for (int j = r; j < kend; j += 16) s += __expf(s_scores[qi * SCW + j] - m);
    #pragma unroll
    for (int o = 8; o; o >>= 1) s += __shfl_xor_sync(0xffffffffu, s, o);
    if (r == 0) { s_red[qi] = m; s_red[16 + qi] = 1.0f / s; }
  }
  __syncthreads();

  // ---- attn prob output ----
  if (write_attn) {
    float* ab = attn_out + ((size_t)(b * NH + h) * SEQ + (size_t)qb * 16) * SEQ;
    for (int idx = tid; idx < 16 * 512; idx += 256) {
      int qi = idx >> 9, j4 = (idx & 511) * 4;
      float m = s_red[qi], inv = s_red[16 + qi];
      float4 p = {0, 0, 0, 0};
      if (j4 < kend) {
        p.x = __expf(s_scores[qi * SCW + j4] - m) * inv;
        if (j4 + 1 < kend) p.y = __expf(s_scores[qi * SCW + j4 + 1] - m) * inv;
        if (j4 + 2 < kend) p.z = __expf(s_scores[qi * SCW + j4 + 2] - m) * inv;
        if (j4 + 3 < kend) p.w = __expf(s_scores[qi * SCW + j4 + 3] - m) * inv;
      }
      *(float4*)(ab + (size_t)qi * SEQ + j4) = p;
    }
  }

  // ---- AV ----
  float oacc[3][2][4];
  #pragma unroll
  for (int t = 0; t < 3; t++)
    #pragma unroll
    for (int nt = 0; nt < 2; nt++)
      #pragma unroll
      for (int j = 0; j < 4; j++) oacc[t][nt][j] = 0.f;

  for (int kc = 0; kc < kend; kc += 128) {
    __syncthreads();
    for (int idx = tid; idx < 128 * 16; idx += 256) {
      int j = idx >> 4, g = idx & 15;
      uint4 vh = {0, 0, 0, 0}, vl = {0, 0, 0, 0};
      if (kc + j < kend) {
        size_t go = ((size_t)(b * SEQ + kc + j) * NKV + hk) * HDIM + g * 8;
        vh = *(const uint4*)(g_vbh + go);
        vl = *(const uint4*)(g_vbl + go);
      }
      *(uint4*)(smc + OFF_KH + j * PAD_STR + g * 16) = vh;
      *(uint4*)(smc + OFF_KL + j * PAD_STR + g * 16) = vl;
    }
    for (int idx = tid; idx < 16 * 64; idx += 256) {
      int r = idx >> 6, c2 = (idx & 63) * 2;
      float m = s_red[r], inv = s_red[16 + r];
      float p0 = 0.f, p1 = 0.f;
      if (kc + c2 < kend)     p0 = __expf(s_scores[r * SCW + kc + c2] - m) * inv;
      if (kc + c2 + 1 < kend) p1 = __expf(s_scores[r * SCW + kc + c2 + 1] - m) * inv;
      __nv_bfloat16 h0 = __float2bfloat16(p0), h1 = __float2bfloat16(p1);
      __nv_bfloat162 hh; hh.x = h0; hh.y = h1;
      __nv_bfloat162 ll;
      ll.x = __float2bfloat16(p0 - __bfloat162float(h0));
      ll.y = __float2bfloat16(p1 - __bfloat162float(h1));
      *(__nv_bfloat162*)(smc + OFF_PH + r * PAD_STR + c2 * 2) = hh;
      *(__nv_bfloat162*)(smc + OFF_PL + r * PAD_STR + c2 * 2) = ll;
    }
    __syncthreads();

    #pragma unroll
    for (int kk = 0; kk < 8; kk++) {
      uint32_t pOff = lrow * PAD_STR + kk * 32 + lhi * 16;
      uint32_t ph[4], pl[4];
      LDSM4(ph, sb + OFF_PH + pOff);
      LDSM4(pl, sb + OFF_PL + pOff);
      uint32_t vOff = (kk * 16 + lrow) * PAD_STR + w * 32 + lhi * 16;
      uint32_t vh[4], vl[4];
      LDSM4T(vh, sb + OFF_KH + vOff);
      LDSM4T(vl, sb + OFF_KL + vOff);
      MMA16816(oacc[0][0], ph, vh[0], vh[1]);
      MMA16816(oacc[0][1], ph, vh[2], vh[3]);
      MMA16816(oacc[1][0], ph, vl[0], vl[1]);
      MMA16816(oacc[1][1], ph, vl[2], vl[3]);
      MMA16816(oacc[2][0], pl, vh[0], vh[1]);
      MMA16816(oacc[2][1], pl, vh[2], vh[3]);
    }
  }

  // epilogue: split ctx bf16 [tok, H*HD]
  {
    int r0 = lane >> 2, c0 = (lane & 3) * 2;
    #pragma unroll
    for (int nt = 0; nt < 2; nt++) {
      int col = w * 16 + nt * 8 + c0;
      #pragma unroll
      for (int half = 0; half < 2; half++) {
        float v0 = oacc[0][nt][2 * half] + oacc[1][nt][2 * half] + oacc[2][nt][2 * half];
        float v1 = oacc[0][nt][2 * half + 1] + oacc[1][nt][2 * half + 1] + oacc[2][nt][2 * half + 1];
        __nv_bfloat16 h0 = __float2bfloat16(v0), h1 = __float2bfloat16(v1);
        __nv_bfloat162 hh; hh.x = h0; hh.y = h1;
        __nv_bfloat162 ll;
        ll.x = __float2bfloat16(v0 - __bfloat162float(h0));
        ll.y = __float2bfloat16(v1 - __bfloat162float(h1));
        size_t o = ((size_t)(b * SEQ + qb * 16 + r0 + half * 8)) * DMODEL
                 + h * HDIM + col;
        *(__nv_bfloat162*)(g_cth + o) = hh;
        *(__nv_bfloat162*)(g_ctl + o) = ll;
      }
    }
  }
}

// ---------------------------------------------------------------------------
extern "C" void kernel_launch(void* const* d_in, const int* in_sizes, int n_in,
                              void* d_out, int out_size) {
  const float* x  = (const float*)d_in[0];
  const float* Wq = (const float*)d_in[1];
  const float* Wk = (const float*)d_in[2];
  const float* Wv = (const float*)d_in[3];
  const float* Wo = (const float*)d_in[4];
  float* out = (float*)d_out;
  float* attn = out + (size_t)NTOK * DMODEL;
  long long need = (long long)NTOK * DMODEL + (long long)BATCH * NH * SEQ * SEQ;
  int write_attn = ((long long)out_size >= need) ? 1 : 0;

  float *gq, *gk;
  __nv_bfloat16 *xh, *xl, *cth, *ctl, *vbh, *vbl;
  __nv_bfloat16 *wqh, *wql, *wkh, *wkl, *wvh, *wvl, *woh, *wol;
  cudaGetSymbolAddress((void**)&gq, g_q);
  cudaGetSymbolAddress((void**)&gk, g_k);
  cudaGetSymbolAddress((void**)&xh, g_xh);
  cudaGetSymbolAddress((void**)&xl, g_xl);
  cudaGetSymbolAddress((void**)&cth, g_cth);
  cudaGetSymbolAddress((void**)&ctl, g_ctl);
  cudaGetSymbolAddress((void**)&vbh, g_vbh);
  cudaGetSymbolAddress((void**)&vbl, g_vbl);
  cudaGetSymbolAddress((void**)&wqh, g_wqh);
  cudaGetSymbolAddress((void**)&wql, g_wql);
  cudaGetSymbolAddress((void**)&wkh, g_wkh);
  cudaGetSymbolAddress((void**)&wkl, g_wkl);
  cudaGetSymbolAddress((void**)&wvh, g_wvh);
  cudaGetSymbolAddress((void**)&wvl, g_wvl);
  cudaGetSymbolAddress((void**)&woh, g_woh);
  cudaGetSymbolAddress((void**)&wol, g_wol);

  cudaFuncSetAttribute(gemm3_kernel, cudaFuncAttributeMaxDynamicSharedMemorySize,
                       GEMM_SMEM);
  cudaFuncSetAttribute(attn_mma_kernel, cudaFuncAttributeMaxDynamicSharedMemorySize,
                       ATTN_SMEM);

  {
    int n = NTOK * DMODEL;
    split_kernel<<<(n + 255) / 256, 256>>>(x, xh, xl, n);
  }
  wsplit_kernel<<<dim3((NH*HDIM)/32, DMODEL/32), dim3(32, 8)>>>(Wq, wqh, wql, DMODEL, NH*HDIM);
  wsplit_kernel<<<dim3((NKV*HDIM)/32, DMODEL/32), dim3(32, 8)>>>(Wk, wkh, wkl, DMODEL, NKV*HDIM);
  wsplit_kernel<<<dim3((NKV*HDIM)/32, DMODEL/32), dim3(32, 8)>>>(Wv, wvh, wvl, DMODEL, NKV*HDIM);
  wsplit_kernel<<<dim3(DMODEL/32, DMODEL/32), dim3(32, 8)>>>(Wo, woh, wol, DMODEL, DMODEL);

  gemm3_kernel<<<dim3((NH*HDIM)/GBN, NTOK/GBM), 256, GEMM_SMEM>>>(
      xh, xl, wqh, wql, gq, nullptr, nullptr, DMODEL, NH*HDIM);
  gemm3_kernel<<<dim3((NKV*HDIM)/GBN, NTOK/GBM), 256, GEMM_SMEM>>>(
      xh, xl, wkh, wkl, gk, nullptr, nullptr, DMODEL, NKV*HDIM);
  gemm3_kernel<<<dim3((NKV*HDIM)/GBN, NTOK/GBM), 256, GEMM_SMEM>>>(
      xh, xl, wvh, wvl, nullptr, vbh, vbl, DMODEL, NKV*HDIM);

  rope_norm_kernel<<<dim3(NTOK, NH + NKV), 64>>>();

  attn_mma_kernel<<<dim3(SEQ / 16, NH, BATCH), 256, ATTN_SMEM>>>(attn, write_attn);

  gemm3_kernel<<<dim3(DMODEL/GBN, NTOK/GBM), 256, GEMM_SMEM>>>(
      cth, ctl, woh, wol, out, nullptr, nullptr, DMODEL, DMODEL);
}